// round 6
// baseline (speedup 1.0000x reference)
#include <cuda_runtime.h>
#include <cuda_fp16.h>
#include <cstdint>
#include <math.h>

#define N_NODES 50000
#define N_EDGES 640000
#define RAW 128
#define HID 256
#define KPAD 320            // 2*RAW+1 padded to multiple of 64
#define PIN_K (RAW + HID)   // 384

// ---------------- scratch (device globals; no allocations allowed) ----------
__device__ __half g_bufA[(size_t)N_NODES * HID];      // node hidden
__device__ float  g_msum[(size_t)N_NODES * HID];
__device__ float  g_tsum[(size_t)N_NODES * 3];
__device__ float  g_cnt[N_NODES];
__device__ __half g_pin[(size_t)N_NODES * PIN_K];
// transposed fp16 weights, [N,K] K-major, packed:
__device__ __half g_wt[409600];
#define WT1_OFF 0         // [256,320]
#define WT2_OFF 81920     // [256,256]
#define WT3_OFF 147456    // [256,256]
#define WT4_OFF 212992    // [256,256]
#define WT5_OFF 278528    // [256,384]
#define WT6_OFF 376832    // [128,256]

__device__ __forceinline__ float silu_f(float x) { return x / (1.0f + __expf(-x)); }

__device__ __forceinline__ uint32_t smem_u32(const void* p) {
    uint32_t a;
    asm("{ .reg .u64 t; cvta.to.shared.u64 t, %1; cvt.u32.u64 %0, t; }" : "=r"(a) : "l"(p));
    return a;
}
__device__ __forceinline__ void cp16(uint32_t dst, const void* src, uint32_t sz) {
    asm volatile("cp.async.cg.shared.global [%0], [%1], 16, %2;" :: "r"(dst), "l"(src), "r"(sz) : "memory");
}
__device__ __forceinline__ void ldsm4(uint32_t& r0, uint32_t& r1, uint32_t& r2, uint32_t& r3,
                                      uint32_t addr) {
    asm volatile("ldmatrix.sync.aligned.m8n8.x4.shared.b16 {%0,%1,%2,%3}, [%4];"
                 : "=r"(r0), "=r"(r1), "=r"(r2), "=r"(r3) : "r"(addr));
}
__device__ __forceinline__ void stsh32(uint32_t addr, uint32_t v) {
    asm volatile("st.shared.b32 [%0], %1;" :: "r"(addr), "r"(v) : "memory");
}
__device__ __forceinline__ void stsh64(uint32_t addr, uint32_t v0, uint32_t v1) {
    asm volatile("st.shared.v2.b32 [%0], {%1,%2};" :: "r"(addr), "r"(v0), "r"(v1) : "memory");
}
__device__ __forceinline__ void stsh128z(uint32_t addr) {
    asm volatile("st.shared.v4.b32 [%0], {%1,%1,%1,%1};" :: "r"(addr), "r"(0u) : "memory");
}
__device__ __forceinline__ void stsh16(uint32_t addr, unsigned short v) {
    asm volatile("st.shared.b16 [%0], %1;" :: "r"(addr), "h"(v) : "memory");
}
__device__ __forceinline__ uint4 ldsh128(uint32_t addr) {
    uint4 v;
    asm volatile("ld.shared.v4.b32 {%0,%1,%2,%3}, [%4];"
                 : "=r"(v.x), "=r"(v.y), "=r"(v.z), "=r"(v.w) : "r"(addr));
    return v;
}

// ================= fused edge kernel =========================================
// SMEM layout (bytes, dynamic):
#define A0_OFF 0            // 5 k-tiles of [128x64] fp16 (swizzled)  80 KB
#define A1_OFF 81920        // 4 k-tiles                              64 KB
#define W_OFF  147456       // 2 weight tiles [128x64]                32 KB
#define SROW_OFF 180224
#define SCOL_OFF 180736
#define CD_OFF   181248     // 128*3 floats
#define W3_OFF   182784     // 256 floats
#define DSM_EDGE 184320

__device__ __forceinline__ void pre_w(uint32_t sb, const __half* W, int ldw, int kt, int tid)
{
    const uint32_t buf = (uint32_t)(kt & 1) * 16384u;
    #pragma unroll
    for (int i = 0; i < 2; i++) {
        const int j = tid + i * 512;
        const int wrow = j >> 3, ch = j & 7;
        const __half* src = W + (size_t)wrow * ldw + kt * 64 + ch * 8;
        const uint32_t dst = sb + W_OFF + buf + (uint32_t)wrow * 128u
                             + (uint32_t)((ch ^ (wrow & 7)) << 4);
        cp16(dst, src, 16);
    }
    asm volatile("cp.async.commit_group;" ::: "memory");
}

// one 128x128 output pass: dst[:, colBase:colBase+128] = silu(src @ W^T + bias)
__device__ void gemm_pass(uint32_t sb, uint32_t srcOff, uint32_t dstOff,
                          const __half* __restrict__ W, int ldw, int nkt,
                          const float* __restrict__ bias, int colBase)
{
    const int tid = threadIdx.x;
    const int wid = tid >> 5, lane = tid & 31;
    const int gid = lane >> 2, ctid = lane & 3;
    const int warpm = wid >> 2, warpn = wid & 3;      // 4x4 warp grid
    const uint32_t fRow = (uint32_t)(lane & 15);
    const uint32_t fHi  = (uint32_t)(lane >> 4);
    const uint32_t fSx  = (uint32_t)(lane & 7);

    float acc[2][4][4];
    #pragma unroll
    for (int i = 0; i < 2; i++)
        #pragma unroll
        for (int j = 0; j < 4; j++)
            #pragma unroll
            for (int q = 0; q < 4; q++) acc[i][j][q] = 0.0f;

    pre_w(sb, W, ldw, 0, tid);
    for (int kt = 0; kt < nkt; kt++) {
        if (kt + 1 < nkt) {
            pre_w(sb, W, ldw, kt + 1, tid);
            asm volatile("cp.async.wait_group 1;" ::: "memory");
        } else {
            asm volatile("cp.async.wait_group 0;" ::: "memory");
        }
        __syncthreads();

        const uint32_t aT = sb + srcOff + (uint32_t)kt * 16384u;
        const uint32_t bT = sb + W_OFF + (uint32_t)(kt & 1) * 16384u;
        #pragma unroll
        for (int kk = 0; kk < 4; kk++) {
            const uint32_t koff = ((((uint32_t)(2 * kk) + fHi) ^ fSx) << 4);
            uint32_t a[2][4], b[4][2];
            #pragma unroll
            for (int mf = 0; mf < 2; mf++)
                ldsm4(a[mf][0], a[mf][1], a[mf][2], a[mf][3],
                      aT + ((uint32_t)(warpm * 32 + mf * 16) + fRow) * 128u + koff);
            #pragma unroll
            for (int p = 0; p < 2; p++)
                ldsm4(b[2*p][0], b[2*p+1][0], b[2*p][1], b[2*p+1][1],
                      bT + ((uint32_t)(warpn * 32 + p * 16) + fRow) * 128u + koff);
            #pragma unroll
            for (int mf = 0; mf < 2; mf++)
                #pragma unroll
                for (int nf = 0; nf < 4; nf++) {
                    asm volatile(
                        "mma.sync.aligned.m16n8k16.row.col.f32.f16.f16.f32 "
                        "{%0,%1,%2,%3}, {%4,%5,%6,%7}, {%8,%9}, {%0,%1,%2,%3};"
                        : "+f"(acc[mf][nf][0]), "+f"(acc[mf][nf][1]),
                          "+f"(acc[mf][nf][2]), "+f"(acc[mf][nf][3])
                        : "r"(a[mf][0]), "r"(a[mf][1]), "r"(a[mf][2]), "r"(a[mf][3]),
                          "r"(b[nf][0]), "r"(b[nf][1]));
                }
        }
        __syncthreads();
    }

    // epilogue: silu(acc + bias) -> fp16 swizzled smem at dstOff
    #pragma unroll
    for (int nf = 0; nf < 4; nf++) {
        const int colG = colBase + warpn * 32 + nf * 8 + ctid * 2;
        const float b0 = bias[colG], b1 = bias[colG + 1];
        const uint32_t tile = (uint32_t)(colG >> 6);
        const uint32_t cc = (uint32_t)(colG & 63);
        #pragma unroll
        for (int mf = 0; mf < 2; mf++)
            #pragma unroll
            for (int h = 0; h < 2; h++) {
                const int row = warpm * 32 + mf * 16 + gid + h * 8;
                float v0 = silu_f(acc[mf][nf][h * 2 + 0] + b0);
                float v1 = silu_f(acc[mf][nf][h * 2 + 1] + b1);
                __half2 hv = __floats2half2_rn(v0, v1);
                const uint32_t addr = sb + dstOff + tile * 16384u + (uint32_t)row * 128u
                                      + (((cc >> 3) ^ (uint32_t)(row & 7)) << 4) + (cc & 7) * 2u;
                stsh32(addr, *(uint32_t*)&hv);
            }
    }
    __syncthreads();
}

__global__ void __launch_bounds__(512, 1)
fused_edge(const int* __restrict__ ei,
           const float* __restrict__ str,
           const float* __restrict__ coord,
           const __half* __restrict__ wt,
           const float* __restrict__ b1, const float* __restrict__ b2,
           const float* __restrict__ b3, const float* __restrict__ b4,
           const float* __restrict__ w3)
{
    extern __shared__ char smem[];
    const uint32_t sb = smem_u32(smem);
    int* srow = (int*)(smem + SROW_OFF);
    int* scol = (int*)(smem + SCOL_OFF);
    float* cds = (float*)(smem + CD_OFF);
    float* w3s = (float*)(smem + W3_OFF);

    const int tid = threadIdx.x;
    const int wid = tid >> 5, lane = tid & 31;
    const int e0 = blockIdx.x * 128;

    // ---- phase 0: indices, w3 ------------------------------------------------
    if (tid < 128)        srow[tid] = ei[e0 + tid];
    else if (tid < 256)   scol[tid - 128] = ei[N_EDGES + e0 + (tid - 128)];
    else                  w3s[tid - 256] = w3[tid - 256];
    __syncthreads();

    // ---- phase 0b: coord diff, d2, pad tile 4 ---------------------------------
    if (tid < 128) {
        const int e = tid;
        const int r = srow[e], c = scol[e];
        const float dx = coord[r*3+0] - coord[c*3+0];
        const float dy = coord[r*3+1] - coord[c*3+1];
        const float dz = coord[r*3+2] - coord[c*3+2];
        cds[e*3+0] = dx; cds[e*3+1] = dy; cds[e*3+2] = dz;
        const uint32_t rowb = sb + A0_OFF + 4u * 16384u + (uint32_t)e * 128u;
        #pragma unroll
        for (int ch = 0; ch < 8; ch++)
            stsh128z(rowb + (uint32_t)((ch ^ (e & 7)) << 4));
        const __half hd2 = __float2half(dx*dx + dy*dy + dz*dz);
        stsh16(rowb + (uint32_t)((0 ^ (e & 7)) << 4), *(const unsigned short*)&hd2);
    }

    // ---- phase 1: gather str rows into A0 cols 0..255 --------------------------
    const float4* s4 = (const float4*)str;
    #pragma unroll
    for (int i = 0; i < 16; i++) {
        const int j = tid + i * 512;          // 0..8191
        const int e = j >> 6;
        const int k = j & 63;                 // float4 index over 256 cols
        const int idx = (k < 32) ? srow[e] : scol[e];
        const float4 v = s4[(size_t)idx * 32 + (k & 31)];
        const __half2 h0 = __floats2half2_rn(v.x, v.y);
        const __half2 h1 = __floats2half2_rn(v.z, v.w);
        const int c0 = k * 4;
        const uint32_t tile = (uint32_t)(c0 >> 6);
        const uint32_t cc = (uint32_t)(c0 & 63);
        const uint32_t addr = sb + A0_OFF + tile * 16384u + (uint32_t)e * 128u
                              + (((cc >> 3) ^ (uint32_t)(e & 7)) << 4) + (cc & 7) * 2u;
        stsh64(addr, *(const uint32_t*)&h0, *(const uint32_t*)&h1);
    }
    __syncthreads();

    // ---- layers --------------------------------------------------------------
    gemm_pass(sb, A0_OFF, A1_OFF, wt + WT1_OFF,             320, 5, b1, 0);
    gemm_pass(sb, A0_OFF, A1_OFF, wt + WT1_OFF + 128*320,   320, 5, b1, 128);
    gemm_pass(sb, A1_OFF, A0_OFF, wt + WT2_OFF,             256, 4, b2, 0);
    gemm_pass(sb, A1_OFF, A0_OFF, wt + WT2_OFF + 128*256,   256, 4, b2, 128);

    // ---- msg scatter (A0 holds msg) + cnt --------------------------------------
    {
        const uint32_t r8 = (uint32_t)(lane >> 3);      // tile 0..3
        const uint32_t c8 = (uint32_t)(lane & 7);       // chunk
        #pragma unroll
        for (int q = 0; q < 8; q++) {
            const int e = wid * 8 + q;
            const int r = srow[e];
            const uint32_t addr = sb + A0_OFF + r8 * 16384u + (uint32_t)e * 128u
                                  + ((c8 ^ (uint32_t)(e & 7)) << 4);
            const uint4 v = ldsh128(addr);
            float* dst = g_msum + (size_t)r * HID + lane * 8;
            const uint32_t w[4] = {v.x, v.y, v.z, v.w};
            #pragma unroll
            for (int t = 0; t < 4; t++) {
                const float2 f = __half22float2(*(const __half2*)&w[t]);
                atomicAdd(dst + t * 2 + 0, f.x);
                atomicAdd(dst + t * 2 + 1, f.y);
            }
        }
        if (tid < 128) atomicAdd(&g_cnt[srow[tid]], 1.0f);
    }

    gemm_pass(sb, A0_OFF, A1_OFF, wt + WT3_OFF,             256, 4, b3, 0);
    gemm_pass(sb, A0_OFF, A1_OFF, wt + WT3_OFF + 128*256,   256, 4, b3, 128);
    gemm_pass(sb, A1_OFF, A0_OFF, wt + WT4_OFF,             256, 4, b4, 0);
    gemm_pass(sb, A1_OFF, A0_OFF, wt + WT4_OFF + 128*256,   256, 4, b4, 128);

    // ---- gate = t2 @ w3; trans scatter -----------------------------------------
    {
        const int e = tid >> 2, q = tid & 3;
        const uint32_t base = sb + A0_OFF + (uint32_t)q * 16384u + (uint32_t)e * 128u;
        float s = 0.0f;
        #pragma unroll
        for (int ch = 0; ch < 8; ch++) {
            const uint4 v = ldsh128(base + (uint32_t)((ch ^ (e & 7)) << 4));
            const float* wv = w3s + q * 64 + ch * 8;
            const uint32_t w[4] = {v.x, v.y, v.z, v.w};
            #pragma unroll
            for (int t = 0; t < 4; t++) {
                const float2 f = __half22float2(*(const __half2*)&w[t]);
                s += f.x * wv[t * 2] + f.y * wv[t * 2 + 1];
            }
        }
        s += __shfl_xor_sync(0xffffffffu, s, 1);
        s += __shfl_xor_sync(0xffffffffu, s, 2);
        if (q < 3)
            atomicAdd(&g_tsum[(size_t)srow[e] * 3 + q], cds[e * 3 + q] * s);
    }
}

// ================= node-side GEMM (from R5, proven) ==========================
#define TILE_B 16384
#define STAGE_B (2 * TILE_B)
#define NSTG 3

template <bool ACT, bool RES, bool HOUT>
__global__ void __launch_bounds__(256, 2)
hgemm(const __half* __restrict__ A, int lda,
      const __half* __restrict__ Bt, int ldb,
      void* __restrict__ Cv, int ldc,
      const float* __restrict__ bias,
      const float* __restrict__ resid, int ldr,
      int M, int K)
{
    extern __shared__ char smem[];
    const uint32_t sb = smem_u32(smem);
    const int tid = threadIdx.x;
    const int wid = tid >> 5, lane = tid & 31;
    const int gid = lane >> 2, ctid = lane & 3;
    const int warpm = wid >> 2, warpn = wid & 3;
    const int bm = blockIdx.y * 128, bn = blockIdx.x * 128;
    const int KT = K >> 6;

    const int sRow = tid >> 1, sHalf = tid & 1;
    const uint32_t sSw = (uint32_t)(sRow & 7);
    const bool aOK = (bm + sRow) < M;
    const __half* aSrcRow = A + (size_t)(aOK ? (bm + sRow) : 0) * lda + sHalf * 32;
    const __half* bSrcRow = Bt + (size_t)(bn + sRow) * ldb + sHalf * 32;
    const uint32_t aDstRow = sb + (uint32_t)sRow * 128;
    const uint32_t bDstRow = aDstRow + TILE_B;

    const uint32_t fRow = (uint32_t)(lane & 15);
    const uint32_t fHi  = (uint32_t)(lane >> 4);
    const uint32_t fSx  = (uint32_t)(lane & 7);
    const uint32_t aFragBase = sb + ((uint32_t)warpm * 64 + fRow) * 128;
    const uint32_t bFragBase = sb + TILE_B + ((uint32_t)warpn * 32 + fRow) * 128;

    float acc[4][4][4];
    #pragma unroll
    for (int i = 0; i < 4; i++)
        #pragma unroll
        for (int j = 0; j < 4; j++)
            #pragma unroll
            for (int q = 0; q < 4; q++) acc[i][j][q] = 0.0f;

    auto stage_load = [&](int kt) {
        const uint32_t soff = (uint32_t)(kt % NSTG) * STAGE_B;
        const __half* aS = aSrcRow + kt * 64;
        const __half* bS = bSrcRow + kt * 64;
        #pragma unroll
        for (int i = 0; i < 4; i++) {
            const uint32_t c = (uint32_t)(sHalf * 4 + i);
            const uint32_t off = ((c ^ sSw) << 4);
            cp16(soff + aDstRow + off, aS + i * 8, aOK ? 16u : 0u);
            cp16(soff + bDstRow + off, bS + i * 8, 16u);
        }
        asm volatile("cp.async.commit_group;" ::: "memory");
    };

    stage_load(0);
    if (KT > 1) stage_load(1);

    for (int kt = 0; kt < KT; kt++) {
        if (kt + 2 < KT) {
            stage_load(kt + 2);
            asm volatile("cp.async.wait_group 2;" ::: "memory");
        } else {
            asm volatile("cp.async.wait_group 0;" ::: "memory");
        }
        __syncthreads();

        const uint32_t soff = (uint32_t)(kt % NSTG) * STAGE_B;
        #pragma unroll
        for (int kk = 0; kk < 4; kk++) {
            const uint32_t kc = (uint32_t)(kk * 2);
            const uint32_t koff = (((kc + fHi) ^ fSx) << 4);
            uint32_t a[4][4], b[4][2];
            #pragma unroll
            for (int mf = 0; mf < 4; mf++)
                ldsm4(a[mf][0], a[mf][1], a[mf][2], a[mf][3],
                      soff + aFragBase + (uint32_t)mf * 2048 + koff);
            #pragma unroll
            for (int p = 0; p < 2; p++)
                ldsm4(b[2*p][0], b[2*p+1][0], b[2*p][1], b[2*p+1][1],
                      soff + bFragBase + (uint32_t)p * 2048 + koff);
            #pragma unroll
            for (int mf = 0; mf < 4; mf++)
                #pragma unroll
                for (int nf = 0; nf < 4; nf++) {
                    asm volatile(
                        "mma.sync.aligned.m16n8k16.row.col.f32.f16.f16.f32 "
                        "{%0,%1,%2,%3}, {%4,%5,%6,%7}, {%8,%9}, {%0,%1,%2,%3};"
                        : "+f"(acc[mf][nf][0]), "+f"(acc[mf][nf][1]),
                          "+f"(acc[mf][nf][2]), "+f"(acc[mf][nf][3])
                        : "r"(a[mf][0]), "r"(a[mf][1]), "r"(a[mf][2]), "r"(a[mf][3]),
                          "r"(b[nf][0]), "r"(b[nf][1]));
                }
        }
        __syncthreads();
    }

    #pragma unroll
    for (int mf = 0; mf < 4; mf++) {
        #pragma unroll
        for (int nf = 0; nf < 4; nf++) {
            const int col0 = bn + warpn * 32 + nf * 8 + ctid * 2;
            const float b0 = bias[col0], b1 = bias[col0 + 1];
            #pragma unroll
            for (int h = 0; h < 2; h++) {
                const int row = bm + warpm * 64 + mf * 16 + gid + h * 8;
                if (row >= M) continue;
                float v0 = acc[mf][nf][h * 2 + 0] + b0;
                float v1 = acc[mf][nf][h * 2 + 1] + b1;
                if (ACT) { v0 = silu_f(v0); v1 = silu_f(v1); }
                if (RES) {
                    v0 += resid[(size_t)row * ldr + col0];
                    v1 += resid[(size_t)row * ldr + col0 + 1];
                }
                if (HOUT) {
                    __half2* out = (__half2*)((__half*)Cv + (size_t)row * ldc + col0);
                    *out = __floats2half2_rn(v0, v1);
                } else {
                    float2* out = (float2*)((float*)Cv + (size_t)row * ldc + col0);
                    *out = make_float2(v0, v1);
                }
            }
        }
    }
}

// ---------------- weight transpose -> fp16 -----------------------------------
__global__ void transpose_h(const float* __restrict__ in, __half* __restrict__ out,
                            int K, int N)
{
    const int i = blockIdx.x * 256 + threadIdx.x;
    if (i >= K * N) return;
    const int n = i / K, k = i - n * K;
    out[i] = __float2half(in[(size_t)k * N + n]);
}
__global__ void transpose_w1(const float* __restrict__ w1, __half* __restrict__ out)
{
    const int i = blockIdx.x * 256 + threadIdx.x;
    if (i >= 256 * KPAD) return;
    const int n = i / KPAD, k = i - n * KPAD;
    out[i] = (k < 2 * RAW + 1) ? __float2half(w1[(size_t)k * HID + n]) : __half(0.0f);
}

// ---------------- build p_in = [str | msg_sum] fp16 --------------------------
__global__ void build_pin(const float* __restrict__ str)
{
    const int idx = blockIdx.x * 256 + threadIdx.x;
    if (idx >= N_NODES * PIN_K) return;
    const int n = idx / PIN_K;
    const int c = idx - n * PIN_K;
    g_pin[idx] = __float2half((c < RAW) ? str[(size_t)n*RAW + c]
                                        : g_msum[(size_t)n*HID + (c - RAW)]);
}

// ---------------- coord epilogue ---------------------------------------------
__global__ void coord_epilogue(const float* __restrict__ coord,
                               float* __restrict__ out_coord)
{
    const int idx = blockIdx.x * 256 + threadIdx.x;
    if (idx >= N_NODES * 3) return;
    const int n = idx / 3;
    out_coord[idx] = coord[idx] + g_tsum[idx] / fmaxf(g_cnt[n], 1.0f);
}

// ---------------- launch ------------------------------------------------------
extern "C" void kernel_launch(void* const* d_in, const int* in_sizes, int n_in,
                              void* d_out, int out_size)
{
    const int*   ei      = (const int*)  d_in[0];
    const float* str     = (const float*)d_in[1];
    const float* coord   = (const float*)d_in[2];
    const float* msg_w1  = (const float*)d_in[3];
    const float* msg_b1  = (const float*)d_in[4];
    const float* msg_w2  = (const float*)d_in[5];
    const float* msg_b2  = (const float*)d_in[6];
    const float* tr_w1   = (const float*)d_in[7];
    const float* tr_b1   = (const float*)d_in[8];
    const float* tr_w2   = (const float*)d_in[9];
    const float* tr_b2   = (const float*)d_in[10];
    const float* tr_w3   = (const float*)d_in[11];
    const float* posi_w1 = (const float*)d_in[12];
    const float* posi_b1 = (const float*)d_in[13];
    const float* posi_w2 = (const float*)d_in[14];
    const float* posi_b2 = (const float*)d_in[15];

    float* out_str   = (float*)d_out;
    float* out_coord = (float*)d_out + (size_t)N_NODES * RAW;

    void *p_bufA, *p_msum, *p_tsum, *p_cnt, *p_pin, *p_wt;
    cudaGetSymbolAddress(&p_bufA, g_bufA);
    cudaGetSymbolAddress(&p_msum, g_msum);
    cudaGetSymbolAddress(&p_tsum, g_tsum);
    cudaGetSymbolAddress(&p_cnt,  g_cnt);
    cudaGetSymbolAddress(&p_pin,  g_pin);
    cudaGetSymbolAddress(&p_wt,   g_wt);
    __half* wt = (__half*)p_wt;

    const int DSM = NSTG * STAGE_B;  // 96 KB
    cudaFuncSetAttribute(fused_edge,
                         cudaFuncAttributeMaxDynamicSharedMemorySize, DSM_EDGE);
    cudaFuncSetAttribute(hgemm<true,false,true>,
                         cudaFuncAttributeMaxDynamicSharedMemorySize, DSM);
    cudaFuncSetAttribute(hgemm<false,true,false>,
                         cudaFuncAttributeMaxDynamicSharedMemorySize, DSM);

    cudaMemsetAsync(p_msum, 0, (size_t)N_NODES * HID * sizeof(float));
    cudaMemsetAsync(p_tsum, 0, (size_t)N_NODES * 3 * sizeof(float));
    cudaMemsetAsync(p_cnt,  0, (size_t)N_NODES * sizeof(float));

    transpose_w1<<<(256*KPAD + 255)/256, 256>>>(msg_w1, wt + WT1_OFF);
    transpose_h<<<(256*256 + 255)/256, 256>>>(msg_w2,  wt + WT2_OFF, 256, 256);
    transpose_h<<<(256*256 + 255)/256, 256>>>(tr_w1,   wt + WT3_OFF, 256, 256);
    transpose_h<<<(256*256 + 255)/256, 256>>>(tr_w2,   wt + WT4_OFF, 256, 256);
    transpose_h<<<(384*256 + 255)/256, 256>>>(posi_w1, wt + WT5_OFF, 384, 256);
    transpose_h<<<(256*128 + 255)/256, 256>>>(posi_w2, wt + WT6_OFF, 256, 128);

    // fused edge pipeline: gather + 4 layers + gate + scatters
    fused_edge<<<N_EDGES / 128, 512, DSM_EDGE>>>(
        ei, str, coord, wt, msg_b1, msg_b2, tr_b1, tr_b2, tr_w3);

    // node MLP
    const int MT_N = (N_NODES + 127) / 128;
    build_pin<<<(N_NODES * PIN_K + 255)/256, 256>>>(str);
    hgemm<true,false,true><<<dim3(2, MT_N), 256, DSM>>>(
        (const __half*)p_pin, PIN_K, wt + WT5_OFF, PIN_K,
        p_bufA, HID, posi_b1, nullptr, 0, N_NODES, PIN_K);
    hgemm<false,true,false><<<dim3(1, MT_N), 256, DSM>>>(
        (const __half*)p_bufA, HID, wt + WT6_OFF, HID,
        out_str, RAW, posi_b2, str, RAW, N_NODES, HID);

    coord_epilogue<<<(N_NODES * 3 + 255)/256, 256>>>(coord, out_coord);
}

// round 8
// speedup vs baseline: 1.2023x; 1.2023x over previous
#include <cuda_runtime.h>
#include <cuda_fp16.h>
#include <cstdint>
#include <math.h>

#define N_NODES 50000
#define N_EDGES 640000
#define RAW 128
#define HID 256
#define KPAD 320            // 2*RAW+1 padded to multiple of 64
#define PIN_K (RAW + HID)   // 384

// ---------------- scratch (device globals; no allocations allowed) ----------
__device__ __half g_strh[(size_t)N_NODES * RAW];      // fp16 copy of str
__device__ __half g_d2pad[(size_t)N_EDGES * 8];       // [d2,0,0,0,0,0,0,0] per edge
__device__ float  g_cdiff[(size_t)N_EDGES * 3];
__device__ float  g_gate[N_EDGES];
__device__ __half g_bufE[(size_t)N_EDGES * HID];      // h1 / t1 / node hidden
__device__ __half g_msg[(size_t)N_EDGES * HID];
__device__ float  g_msum[(size_t)N_NODES * HID];
__device__ float  g_tsum[(size_t)N_NODES * 3];
__device__ float  g_cnt[N_NODES];
__device__ __half g_pin[(size_t)N_NODES * PIN_K];
__device__ __half g_wt[409600];
#define WT1_OFF 0         // [256,320]
#define WT2_OFF 81920     // [256,256]
#define WT3_OFF 147456    // [256,256]
#define WT4_OFF 212992    // [256,256]
#define WT5_OFF 278528    // [256,384]
#define WT6_OFF 376832    // [128,256]

__device__ __forceinline__ float silu_f(float x) { return x / (1.0f + __expf(-x)); }

__device__ __forceinline__ uint32_t smem_u32(const void* p) {
    uint32_t a;
    asm("{ .reg .u64 t; cvta.to.shared.u64 t, %1; cvt.u32.u64 %0, t; }" : "=r"(a) : "l"(p));
    return a;
}
__device__ __forceinline__ void cp16(uint32_t dst, const void* src, uint32_t sz) {
    asm volatile("cp.async.cg.shared.global [%0], [%1], 16, %2;" :: "r"(dst), "l"(src), "r"(sz) : "memory");
}
__device__ __forceinline__ void ldsm4(uint32_t& r0, uint32_t& r1, uint32_t& r2, uint32_t& r3,
                                      uint32_t addr) {
    asm volatile("ldmatrix.sync.aligned.m8n8.x4.shared.b16 {%0,%1,%2,%3}, [%4];"
                 : "=r"(r0), "=r"(r1), "=r"(r2), "=r"(r3) : "r"(addr));
}

// ================= FP16 mma.sync GEMM with fused boundaries ==================
// C[M,Ntot] = act(A@Bt^T + bias) variants.
// GATHER: A rows assembled from g_strh via edge indices + d2 column.
// MSUM: epilogue atomically accumulates into msum[ei[row]*HID+col].
// GATE: no C store; epilogue accumulates dot(row, w3) into gate[row].
#define TILE_B 16384
#define STAGE_B (2 * TILE_B)
#define NSTG 3

template <bool GATHER, bool ACT, bool MSUM, bool GATE, bool RES, bool HOUT>
__global__ void __launch_bounds__(256, 2)
hgemm(const __half* __restrict__ A, int lda,
      const __half* __restrict__ Bt, int ldb,
      void* __restrict__ Cv, int ldc,
      const float* __restrict__ bias,
      const float* __restrict__ resid, int ldr,
      int M, int K,
      const int* __restrict__ ei,
      const __half* __restrict__ strh,
      const __half* __restrict__ d2pad,
      const float* __restrict__ w3,
      float* __restrict__ msum,
      float* __restrict__ gate)
{
    extern __shared__ char smem[];
    const uint32_t sb = smem_u32(smem);
    const int tid = threadIdx.x;
    const int wid = tid >> 5, lane = tid & 31;
    const int gid = lane >> 2, ctid = lane & 3;
    const int warpm = wid >> 2, warpn = wid & 3;
    const int bm = blockIdx.y * 128, bn = blockIdx.x * 128;
    const int KT = K >> 6;

    const int sRow = tid >> 1, sHalf = tid & 1;
    const uint32_t sSw = (uint32_t)(sRow & 7);
    const uint32_t aDstRow = sb + (uint32_t)sRow * 128;
    const uint32_t bDstRow = aDstRow + TILE_B;

    // A source setup
    const __half *aSrcRow = nullptr, *aR = nullptr, *aC = nullptr, *d2p = nullptr;
    bool aOK = true;
    if (GATHER) {
        const int e = bm + sRow;
        const int rI = ei[e], cI = ei[N_EDGES + e];
        aR = strh + (size_t)rI * RAW;
        aC = strh + (size_t)cI * RAW;
        d2p = d2pad + (size_t)e * 8;
    } else {
        aOK = (bm + sRow) < M;
        aSrcRow = A + (size_t)(aOK ? (bm + sRow) : 0) * lda + sHalf * 32;
    }
    const __half* bSrcRow = Bt + (size_t)(bn + sRow) * ldb + sHalf * 32;

    const uint32_t fRow = (uint32_t)(lane & 15);
    const uint32_t fHi  = (uint32_t)(lane >> 4);
    const uint32_t fSx  = (uint32_t)(lane & 7);
    const uint32_t aFragBase = sb + ((uint32_t)warpm * 64 + fRow) * 128;
    const uint32_t bFragBase = sb + TILE_B + ((uint32_t)warpn * 32 + fRow) * 128;

    float acc[4][4][4];
    #pragma unroll
    for (int i = 0; i < 4; i++)
        #pragma unroll
        for (int j = 0; j < 4; j++)
            #pragma unroll
            for (int q = 0; q < 4; q++) acc[i][j][q] = 0.0f;

    auto stage_load = [&](int kt) {
        const uint32_t soff = (uint32_t)(kt % NSTG) * STAGE_B;
        #pragma unroll
        for (int i = 0; i < 4; i++) {
            const uint32_t c = (uint32_t)(sHalf * 4 + i);
            const uint32_t off = ((c ^ sSw) << 4);
            if (GATHER) {
                if (kt < 2)      cp16(soff + aDstRow + off, aR + kt * 64 + c * 8, 16u);
                else if (kt < 4) cp16(soff + aDstRow + off, aC + (kt - 2) * 64 + c * 8, 16u);
                else             cp16(soff + aDstRow + off, d2p, (c == 0) ? 16u : 0u);
            } else {
                cp16(soff + aDstRow + off, aSrcRow + kt * 64 + i * 8, aOK ? 16u : 0u);
            }
            cp16(soff + bDstRow + off, bSrcRow + kt * 64 + i * 8, 16u);
        }
        asm volatile("cp.async.commit_group;" ::: "memory");
    };

    stage_load(0);
    if (KT > 1) stage_load(1);

    for (int kt = 0; kt < KT; kt++) {
        if (kt + 2 < KT) {
            stage_load(kt + 2);
            asm volatile("cp.async.wait_group 2;" ::: "memory");
        } else {
            asm volatile("cp.async.wait_group 0;" ::: "memory");
        }
        __syncthreads();

        const uint32_t soff = (uint32_t)(kt % NSTG) * STAGE_B;
        #pragma unroll
        for (int kk = 0; kk < 4; kk++) {
            const uint32_t kc = (uint32_t)(kk * 2);
            const uint32_t koff = (((kc + fHi) ^ fSx) << 4);
            uint32_t a[4][4], b[4][2];
            #pragma unroll
            for (int mf = 0; mf < 4; mf++)
                ldsm4(a[mf][0], a[mf][1], a[mf][2], a[mf][3],
                      soff + aFragBase + (uint32_t)mf * 2048 + koff);
            #pragma unroll
            for (int p = 0; p < 2; p++)
                ldsm4(b[2*p][0], b[2*p+1][0], b[2*p][1], b[2*p+1][1],
                      soff + bFragBase + (uint32_t)p * 2048 + koff);
            #pragma unroll
            for (int mf = 0; mf < 4; mf++)
                #pragma unroll
                for (int nf = 0; nf < 4; nf++) {
                    asm volatile(
                        "mma.sync.aligned.m16n8k16.row.col.f32.f16.f16.f32 "
                        "{%0,%1,%2,%3}, {%4,%5,%6,%7}, {%8,%9}, {%0,%1,%2,%3};"
                        : "+f"(acc[mf][nf][0]), "+f"(acc[mf][nf][1]),
                          "+f"(acc[mf][nf][2]), "+f"(acc[mf][nf][3])
                        : "r"(a[mf][0]), "r"(a[mf][1]), "r"(a[mf][2]), "r"(a[mf][3]),
                          "r"(b[nf][0]), "r"(b[nf][1]));
                }
        }
        __syncthreads();
    }

    // ---- epilogue: per (mf,h) row, loop nf cols ------------------------------
    #pragma unroll
    for (int mf = 0; mf < 4; mf++) {
        #pragma unroll
        for (int h = 0; h < 2; h++) {
            const int row = bm + warpm * 64 + mf * 16 + gid + h * 8;
            const bool rowOK = GATHER ? true : (row < M);
            float gp = 0.0f;
            int srowE = 0;
            if (MSUM && rowOK) srowE = ei[row];
            #pragma unroll
            for (int nf = 0; nf < 4; nf++) {
                const int col0 = bn + warpn * 32 + nf * 8 + ctid * 2;
                float v0 = acc[mf][nf][h * 2 + 0] + bias[col0];
                float v1 = acc[mf][nf][h * 2 + 1] + bias[col0 + 1];
                if (ACT) { v0 = silu_f(v0); v1 = silu_f(v1); }
                if (RES && rowOK) {
                    v0 += resid[(size_t)row * ldr + col0];
                    v1 += resid[(size_t)row * ldr + col0 + 1];
                }
                if (HOUT && rowOK) {
                    __half2* out = (__half2*)((__half*)Cv + (size_t)row * ldc + col0);
                    *out = __floats2half2_rn(v0, v1);
                } else if (!HOUT && !GATE && rowOK) {
                    float2* out = (float2*)((float*)Cv + (size_t)row * ldc + col0);
                    *out = make_float2(v0, v1);
                }
                if (MSUM && rowOK) {
                    atomicAdd(&msum[(size_t)srowE * HID + col0], v0);
                    atomicAdd(&msum[(size_t)srowE * HID + col0 + 1], v1);
                }
                if (GATE) gp += v0 * w3[col0] + v1 * w3[col0 + 1];
            }
            if (GATE) {
                gp += __shfl_xor_sync(0xffffffffu, gp, 1);
                gp += __shfl_xor_sync(0xffffffffu, gp, 2);
                if (ctid == 0) atomicAdd(&gate[row], gp);
            }
        }
    }
}

// ---------------- small kernels ----------------------------------------------
__global__ void conv_str(const float* __restrict__ str)
{
    const int i = blockIdx.x * 256 + threadIdx.x;
    if (i < N_NODES * RAW) g_strh[i] = __float2half(str[i]);
}

__global__ void edge_pre(const int* __restrict__ ei, const float* __restrict__ coord)
{
    const int e = blockIdx.x * 256 + threadIdx.x;
    if (e >= N_EDGES) return;
    const int r = ei[e], c = ei[N_EDGES + e];
    const float dx = coord[r*3+0] - coord[c*3+0];
    const float dy = coord[r*3+1] - coord[c*3+1];
    const float dz = coord[r*3+2] - coord[c*3+2];
    g_cdiff[(size_t)e*3+0] = dx;
    g_cdiff[(size_t)e*3+1] = dy;
    g_cdiff[(size_t)e*3+2] = dz;
    const __half2 d2 = __floats2half2_rn(dx*dx + dy*dy + dz*dz, 0.0f);
    uint4 v; v.x = *(const uint32_t*)&d2; v.y = 0; v.z = 0; v.w = 0;
    *(uint4*)(g_d2pad + (size_t)e * 8) = v;
    atomicAdd(&g_cnt[r], 1.0f);
}

__global__ void trans_scatter(const int* __restrict__ ei)
{
    const int e = blockIdx.x * 256 + threadIdx.x;
    if (e >= N_EDGES) return;
    const float g = g_gate[e];
    const int r = ei[e];
    atomicAdd(&g_tsum[(size_t)r*3+0], g_cdiff[(size_t)e*3+0] * g);
    atomicAdd(&g_tsum[(size_t)r*3+1], g_cdiff[(size_t)e*3+1] * g);
    atomicAdd(&g_tsum[(size_t)r*3+2], g_cdiff[(size_t)e*3+2] * g);
}

__global__ void transpose_h(const float* __restrict__ in, __half* __restrict__ out,
                            int K, int N)
{
    const int i = blockIdx.x * 256 + threadIdx.x;
    if (i >= K * N) return;
    const int n = i / K, k = i - n * K;
    out[i] = __float2half(in[(size_t)k * N + n]);
}
__global__ void transpose_w1(const float* __restrict__ w1, __half* __restrict__ out)
{
    const int i = blockIdx.x * 256 + threadIdx.x;
    if (i >= 256 * KPAD) return;
    const int n = i / KPAD, k = i - n * KPAD;
    out[i] = (k < 2 * RAW + 1) ? __float2half(w1[(size_t)k * HID + n]) : __half(0.0f);
}

__global__ void build_pin(const float* __restrict__ str)
{
    const int idx = blockIdx.x * 256 + threadIdx.x;
    if (idx >= N_NODES * PIN_K) return;
    const int n = idx / PIN_K;
    const int c = idx - n * PIN_K;
    g_pin[idx] = __float2half((c < RAW) ? str[(size_t)n*RAW + c]
                                        : g_msum[(size_t)n*HID + (c - RAW)]);
}

__global__ void coord_epilogue(const float* __restrict__ coord,
                               float* __restrict__ out_coord)
{
    const int idx = blockIdx.x * 256 + threadIdx.x;
    if (idx >= N_NODES * 3) return;
    const int n = idx / 3;
    out_coord[idx] = coord[idx] + g_tsum[idx] / fmaxf(g_cnt[n], 1.0f);
}

// ---------------- launch ------------------------------------------------------
extern "C" void kernel_launch(void* const* d_in, const int* in_sizes, int n_in,
                              void* d_out, int out_size)
{
    const int*   ei      = (const int*)  d_in[0];
    const float* str     = (const float*)d_in[1];
    const float* coord   = (const float*)d_in[2];
    const float* msg_w1  = (const float*)d_in[3];
    const float* msg_b1  = (const float*)d_in[4];
    const float* msg_w2  = (const float*)d_in[5];
    const float* msg_b2  = (const float*)d_in[6];
    const float* tr_w1   = (const float*)d_in[7];
    const float* tr_b1   = (const float*)d_in[8];
    const float* tr_w2   = (const float*)d_in[9];
    const float* tr_b2   = (const float*)d_in[10];
    const float* tr_w3   = (const float*)d_in[11];
    const float* posi_w1 = (const float*)d_in[12];
    const float* posi_b1 = (const float*)d_in[13];
    const float* posi_w2 = (const float*)d_in[14];
    const float* posi_b2 = (const float*)d_in[15];

    float* out_str   = (float*)d_out;
    float* out_coord = (float*)d_out + (size_t)N_NODES * RAW;

    void *p_strh, *p_d2pad, *p_bufE, *p_msg, *p_msum, *p_tsum, *p_cnt, *p_gate, *p_pin, *p_wt;
    cudaGetSymbolAddress(&p_strh,  g_strh);
    cudaGetSymbolAddress(&p_d2pad, g_d2pad);
    cudaGetSymbolAddress(&p_bufE,  g_bufE);
    cudaGetSymbolAddress(&p_msg,   g_msg);
    cudaGetSymbolAddress(&p_msum,  g_msum);
    cudaGetSymbolAddress(&p_tsum,  g_tsum);
    cudaGetSymbolAddress(&p_cnt,   g_cnt);
    cudaGetSymbolAddress(&p_gate,  g_gate);
    cudaGetSymbolAddress(&p_pin,   g_pin);
    cudaGetSymbolAddress(&p_wt,    g_wt);
    __half* wt = (__half*)p_wt;

    const int DSM = NSTG * STAGE_B;  // 96 KB

    #define SETSMEM(k) cudaFuncSetAttribute(k, cudaFuncAttributeMaxDynamicSharedMemorySize, DSM)
    SETSMEM((hgemm<true,true,false,false,false,true>));
    SETSMEM((hgemm<false,true,true,false,false,true>));
    SETSMEM((hgemm<false,true,false,false,false,true>));
    SETSMEM((hgemm<false,true,false,true,false,false>));
    SETSMEM((hgemm<false,false,false,false,true,false>));
    #undef SETSMEM

    cudaMemsetAsync(p_msum, 0, (size_t)N_NODES * HID * sizeof(float));
    cudaMemsetAsync(p_tsum, 0, (size_t)N_NODES * 3 * sizeof(float));
    cudaMemsetAsync(p_cnt,  0, (size_t)N_NODES * sizeof(float));
    cudaMemsetAsync(p_gate, 0, (size_t)N_EDGES * sizeof(float));

    transpose_w1<<<(256*KPAD + 255)/256, 256>>>(msg_w1, wt + WT1_OFF);
    transpose_h<<<(256*256 + 255)/256, 256>>>(msg_w2,  wt + WT2_OFF, 256, 256);
    transpose_h<<<(256*256 + 255)/256, 256>>>(tr_w1,   wt + WT3_OFF, 256, 256);
    transpose_h<<<(256*256 + 255)/256, 256>>>(tr_w2,   wt + WT4_OFF, 256, 256);
    transpose_h<<<(384*256 + 255)/256, 256>>>(posi_w1, wt + WT5_OFF, 384, 256);
    transpose_h<<<(256*128 + 255)/256, 256>>>(posi_w2, wt + WT6_OFF, 256, 128);
    conv_str<<<(N_NODES*RAW + 255)/256, 256>>>(str);
    edge_pre<<<(N_EDGES + 255)/256, 256>>>(ei, coord);

    const int MT_E = N_EDGES / 128;            // 5000
    const int MT_N = (N_NODES + 127) / 128;    // 391

    // L1: h1 = silu([str_r|str_c|d2] @ w1^T + b1)  -- gather fused
    hgemm<true,true,false,false,false,true><<<dim3(2, MT_E), 256, DSM>>>(
        nullptr, 0, wt + WT1_OFF, KPAD, p_bufE, HID, msg_b1, nullptr, 0,
        N_EDGES, KPAD, ei, (const __half*)p_strh, (const __half*)p_d2pad,
        nullptr, nullptr, nullptr);
    // L2: msg = silu(h1 @ w2^T + b2)  -- msum atomics fused
    hgemm<false,true,true,false,false,true><<<dim3(2, MT_E), 256, DSM>>>(
        (const __half*)p_bufE, HID, wt + WT2_OFF, HID, p_msg, HID, msg_b2, nullptr, 0,
        N_EDGES, HID, ei, nullptr, nullptr, nullptr, (float*)p_msum, nullptr);
    // L3: t1 = silu(msg @ tr_w1^T + b1)
    hgemm<false,true,false,false,false,true><<<dim3(2, MT_E), 256, DSM>>>(
        (const __half*)p_msg, HID, wt + WT3_OFF, HID, p_bufE, HID, tr_b1, nullptr, 0,
        N_EDGES, HID, nullptr, nullptr, nullptr, nullptr, nullptr, nullptr);
    // L4: gate partials = silu(t1 @ tr_w2^T + b2) . w3  -- no store (HOUT=false!)
    hgemm<false,true,false,true,false,false><<<dim3(2, MT_E), 256, DSM>>>(
        (const __half*)p_bufE, HID, wt + WT4_OFF, HID, nullptr, 0, tr_b2, nullptr, 0,
        N_EDGES, HID, nullptr, nullptr, nullptr, tr_w3, nullptr, (float*)p_gate);

    trans_scatter<<<(N_EDGES + 255)/256, 256>>>(ei);

    // node MLP
    build_pin<<<(N_NODES * PIN_K + 255)/256, 256>>>(str);
    hgemm<false,true,false,false,false,true><<<dim3(2, MT_N), 256, DSM>>>(
        (const __half*)p_pin, PIN_K, wt + WT5_OFF, PIN_K, p_bufE, HID, posi_b1, nullptr, 0,
        N_NODES, PIN_K, nullptr, nullptr, nullptr, nullptr, nullptr, nullptr);
    hgemm<false,false,false,false,true,false><<<dim3(1, MT_N), 256, DSM>>>(
        (const __half*)p_bufE, HID, wt + WT6_OFF, HID, out_str, RAW, posi_b2, str, RAW,
        N_NODES, HID, nullptr, nullptr, nullptr, nullptr, nullptr, nullptr);

    coord_epilogue<<<(N_NODES * 3 + 255)/256, 256>>>(coord, out_coord);
}